// round 7
// baseline (speedup 1.0000x reference)
#include <cuda_runtime.h>

// Sineconv: out[b,l,f] = sum_{w=0}^{64} x[b, l + 2f + ((f+w)>>5)] * sines[f, l+w]
//                        + x[b, l+32] * res_kernel[f]
// sines[f,s] = amplitude[f] * sin( ((frequency[f]*19000)*2pi) * sine_range[s] + phases[f]*2pi )
//
// x factor is piecewise-constant in w over 3 ranges -> each output needs
// 3 contiguous range-sums of sines + residual.
//
// R7: K1 computes the GLOBAL exclusive prefix sum of each sine row (32 blocks,
// 1024 thr: 16-sample serial prefix -> warp scan -> block scan -> coalesced
// write via smem transpose). K2 has NO scan: copies its prefix window with 5
// coalesced LDG/warp and runs the conflict-free epilogue. Differences of
// prefixes 65 apart cancel shared rounding history -> fp32 global prefix safe.

#define S_TOTAL 16384
#define L_OUT   16320
#define F_N     32
#define B_N     4
#define TILE_L  64
#define FG      8               // features per block (K2)
#define NPP     132             // Psh row stride
#define XW      (TILE_L + 68)   // padded x stage width
#define PSTRIDE 16512           // prefix row stride (>= 16385)

__device__ float g_pref[F_N * PSTRIDE];   // P[f][j] = sum_{s<j} sine[f][s], j=0..16384

// Accurate sinf via fp32 FMA Cody-Waite (exact internal products).
// |arg| <= ~1e5 here: total reduction error ~6e-8 rad.
__device__ __forceinline__ float acc_sinf(float a) {
    float kf = rintf(a * 0.63661977236758134f);          // 2/pi
    float r  = fmaf(-kf, 1.57079637050628662e+0f, a);    // c1 = float(pi/2)
    r        = fmaf(-kf, -4.37113900018624283e-8f, r);   // c2 = float(pi/2 - c1)
    int   q  = (int)kf;
    float r2 = r * r;
    float sp = fmaf(r2, fmaf(r2, fmaf(r2, -1.9841269841e-4f, 8.3333333333e-3f),
                             -1.6666666667e-1f), 1.0f);
    float s  = r * sp;
    float c  = fmaf(r2, fmaf(r2, fmaf(r2, fmaf(r2, 2.4801587302e-5f, -1.3888888889e-3f),
                             4.1666666667e-2f), -5.0e-1f), 1.0f);
    float v = (q & 1) ? c : s;
    return (q & 2) ? -v : v;
}

// ---- kernel 1: per-row sine prefix. grid 32 (one block per f), 1024 thr ----
__global__ __launch_bounds__(1024) void sine_prefix_kernel(
    const float* __restrict__ sr,
    const float* __restrict__ phases,
    const float* __restrict__ amplitude,
    const float* __restrict__ frequency)
{
    __shared__ float wsum[32];
    __shared__ float st[512 * 17];     // half-block transpose staging (34.8 KB)

    const float TWO_PI = 6.28318530717958647692f;
    const int f    = blockIdx.x;
    const int tid  = threadIdx.x;
    const int lane = tid & 31;
    const int wp   = tid >> 5;

    // Replicate reference fp32 rounding: ((freq*19000)*2pi)*sr + ph
    float w2  = __fmul_rn(__fmul_rn(frequency[f], 19000.0f), TWO_PI);
    float ph  = __fmul_rn(phases[f], TWO_PI);
    float amp = amplitude[f];

    // 16 consecutive samples per thread: j = tid*16 + k; inclusive local prefix
    float loc[16];
    float run = 0.0f;
    const float4* sr4 = (const float4*)sr;
#pragma unroll
    for (int q = 0; q < 4; q++) {
        float4 sv = sr4[tid * 4 + q];
        run += __fmul_rn(amp, acc_sinf(__fadd_rn(__fmul_rn(w2, sv.x), ph))); loc[q*4+0] = run;
        run += __fmul_rn(amp, acc_sinf(__fadd_rn(__fmul_rn(w2, sv.y), ph))); loc[q*4+1] = run;
        run += __fmul_rn(amp, acc_sinf(__fadd_rn(__fmul_rn(w2, sv.z), ph))); loc[q*4+2] = run;
        run += __fmul_rn(amp, acc_sinf(__fadd_rn(__fmul_rn(w2, sv.w), ph))); loc[q*4+3] = run;
    }
    // warp scan of per-thread totals
    float t = run;
#pragma unroll
    for (int off = 1; off < 32; off <<= 1) {
        float n = __shfl_up_sync(0xFFFFFFFFu, t, off);
        if (lane >= off) t += n;
    }
    float wexcl = t - run;
    if (lane == 31) wsum[wp] = t;
    __syncthreads();
    if (wp == 0) {
        float v = wsum[lane];
        float t2 = v;
#pragma unroll
        for (int off = 1; off < 32; off <<= 1) {
            float n = __shfl_up_sync(0xFFFFFFFFu, t2, off);
            if (lane >= off) t2 += n;
        }
        wsum[lane] = t2 - v;               // exclusive warp offsets
    }
    __syncthreads();
    const float base = wsum[wp] + wexcl;   // exclusive prefix before sample tid*16

    float* prow = g_pref + f * PSTRIDE;
    if (tid == 0) prow[0] = 0.0f;

    // coalesced write of P[j]=base+loc (j = tid*16+1 .. +16) via smem transpose,
    // two halves of 512 threads so staging fits in static smem.
#pragma unroll
    for (int h = 0; h < 2; h++) {
        if ((tid >> 9) == h) {
            int tl = tid & 511;
#pragma unroll
            for (int k = 0; k < 16; k++) st[tl * 17 + k] = base + loc[k];
        }
        __syncthreads();
#pragma unroll
        for (int m = 0; m < 8; m++) {
            int jl = m * 1024 + tid;                   // local sample in half
            prow[h * 8192 + jl + 1] = st[(jl >> 4) * 17 + (jl & 15)];
        }
        __syncthreads();
    }
}

// ---- kernel 2: window copy + epilogue. grid (255, 4), 256 thr, NO scan ----
__global__ __launch_bounds__(256) void sineconv_kernel(
    const float* __restrict__ x,          // (B, S, 1)
    const float* __restrict__ res_kernel, // (32,)
    float* __restrict__ out)              // (B, L, F)
{
    __shared__ float Psh[FG][NPP];     // Psh[w][j] = P[f][s0+j], j = 0..128
    __shared__ float xsh[B_N][XW];

    const int tid  = threadIdx.x;
    const int lane = tid & 31;
    const int warp = tid >> 5;
    const int s0   = blockIdx.x * TILE_L;
    const int fg0  = blockIdx.y * FG;

    // ---- stage x halo (s in [s0, s0+130]) ----
    for (int idx = tid; idx < B_N * (TILE_L + 67); idx += 256) {
        int b = idx / (TILE_L + 67);
        int i = idx - b * (TILE_L + 67);
        int s = s0 + i;
        xsh[b][i] = (s < S_TOTAL) ? x[b * S_TOTAL + s] : 0.0f;
    }

    // ---- stage prefix window: warp w copies row fg0+w (coalesced) ----
    {
        const float* prow = g_pref + (fg0 + warp) * PSTRIDE + s0;  // s0+128 <= 16384
#pragma unroll
        for (int p = 0; p < 4; p++)
            Psh[warp][lane + 32 * p] = prow[lane + 32 * p];
        if (lane == 0) Psh[warp][128] = prow[128];
    }
    __syncthreads();

    // ---- epilogue: thread -> (fl = tid&7, i0 = tid>>3), 2 l-passes x 4 batches ----
    const int fl = tid & 7;
    const int f  = fg0 + fl;
    const int i0 = tid >> 3;             // 0..31
    const float rk = res_kernel[f];
    const int i32 = 32 - f;
    const int i64 = 64 - f;

#pragma unroll
    for (int p = 0; p < 2; p++) {
        int i = i0 + p * 32;             // local l index, 0..63
        int l = s0 + i;
        float p0 = Psh[fl][i];
        float pa = Psh[fl][i + i32];
        float pb = Psh[fl][i + i64];
        float p3 = Psh[fl][i + 65];
        float A0 = pa - p0;              // sum sines[f, l .. l+31-f]
        float A1 = pb - pa;              // sum sines[f, l+32-f .. l+63-f]
        float A2 = p3 - pb;              // sum sines[f, l+64-f .. l+64]
        int xb = i + 2 * f;
#pragma unroll
        for (int b = 0; b < B_N; b++) {
            float r = fmaf(xsh[b][xb],     A0,
                      fmaf(xsh[b][xb + 1], A1,
                      fmaf(xsh[b][xb + 2], A2,
                           xsh[b][i + 32] * rk)));
            out[(b * L_OUT + l) * F_N + f] = r;
        }
    }
}

extern "C" void kernel_launch(void* const* d_in, const int* in_sizes, int n_in,
                              void* d_out, int out_size) {
    const float* x    = (const float*)d_in[0];
    const float* sr   = (const float*)d_in[1];
    const float* ph   = (const float*)d_in[2];
    const float* amp  = (const float*)d_in[3];
    const float* freq = (const float*)d_in[4];
    const float* rk   = (const float*)d_in[5];
    float* out = (float*)d_out;

    sine_prefix_kernel<<<F_N, 1024>>>(sr, ph, amp, freq);

    dim3 g2(L_OUT / TILE_L, F_N / FG);
    sineconv_kernel<<<g2, 256>>>(x, rk, out);
}

// round 8
// speedup vs baseline: 1.3552x; 1.3552x over previous
#include <cuda_runtime.h>

// Sineconv: out[b,l,f] = sum_{w=0}^{64} x[b, l + 2f + ((f+w)>>5)] * sines[f, l+w]
//                        + x[b, l+32] * res_kernel[f]
// sines[f,s] = amplitude[f] * sin( ((frequency[f]*19000)*2pi) * sine_range[s] + phases[f]*2pi )
//
// x factor is piecewise-constant in w over 3 ranges -> each output needs
// 3 contiguous range-sums of sines (local fp32 prefix scan) + residual.
//
// R8: K1 = fully parallel sine table (512 CTAs). K2 = R6 scan+epilogue, but
// with front-batched LDG count per warp cut from ~8 to ~2 (one LDG.128 for x
// stage, one for the sine window) to kill the cross-CTA L1tex-queue spread
// that held K2 at ~8us regardless of instruction count. Halo corrected to
// exactly 128 floats (max x index = i+2f+2 = 127); scan writes via one
// aligned STS.128/lane of exclusive prefixes.

#define S_TOTAL 16384
#define L_OUT   16320
#define F_N     32
#define B_N     4
#define TILE_L  64
#define FG      8               // features per block (K2)
#define NPP     132             // Psh row stride (528B: 16B-aligned rows, CF epilogue)
#define XW      132             // xsh row stride (only 0..127 used)

__device__ float g_sine[F_N * S_TOTAL];   // 2 MB table: amp[f]*sin(arg[f,s])

// Accurate sinf via fp32 FMA Cody-Waite (exact internal products).
// |arg| <= ~1e5 here: total reduction error ~6e-8 rad.
__device__ __forceinline__ float acc_sinf(float a) {
    float kf = rintf(a * 0.63661977236758134f);          // 2/pi
    float r  = fmaf(-kf, 1.57079637050628662e+0f, a);    // c1 = float(pi/2)
    r        = fmaf(-kf, -4.37113900018624283e-8f, r);   // c2 = float(pi/2 - c1)
    int   q  = (int)kf;
    float r2 = r * r;
    float sp = fmaf(r2, fmaf(r2, fmaf(r2, -1.9841269841e-4f, 8.3333333333e-3f),
                             -1.6666666667e-1f), 1.0f);
    float s  = r * sp;
    float c  = fmaf(r2, fmaf(r2, fmaf(r2, fmaf(r2, 2.4801587302e-5f, -1.3888888889e-3f),
                             4.1666666667e-2f), -5.0e-1f), 1.0f);
    float v = (q & 1) ? c : s;
    return (q & 2) ? -v : v;
}

// ---- kernel 1: sine table. grid (16, 32), 256 thr; 4 sines/thread ----
__global__ __launch_bounds__(256) void sine_table_kernel(
    const float* __restrict__ sr,
    const float* __restrict__ phases,
    const float* __restrict__ amplitude,
    const float* __restrict__ frequency)
{
    const float TWO_PI = 6.28318530717958647692f;
    const int f  = blockIdx.y;
    const int s4 = blockIdx.x * 256 + threadIdx.x;        // float4 index
    // Replicate reference fp32 rounding: ((freq*19000)*2pi)*sr + ph
    float w2  = __fmul_rn(__fmul_rn(frequency[f], 19000.0f), TWO_PI);
    float ph  = __fmul_rn(phases[f], TWO_PI);
    float amp = amplitude[f];

    float4 sv = ((const float4*)sr)[s4];
    float4 o;
    o.x = __fmul_rn(amp, acc_sinf(__fadd_rn(__fmul_rn(w2, sv.x), ph)));
    o.y = __fmul_rn(amp, acc_sinf(__fadd_rn(__fmul_rn(w2, sv.y), ph)));
    o.z = __fmul_rn(amp, acc_sinf(__fadd_rn(__fmul_rn(w2, sv.z), ph)));
    o.w = __fmul_rn(amp, acc_sinf(__fadd_rn(__fmul_rn(w2, sv.w), ph)));
    ((float4*)(g_sine + f * S_TOTAL))[s4] = o;
}

// ---- kernel 2: window scan + epilogue. grid (255, 4), 256 thr ----
__global__ __launch_bounds__(256) void sineconv_kernel(
    const float* __restrict__ x,          // (B, S, 1)
    const float* __restrict__ res_kernel, // (32,)
    float* __restrict__ out)              // (B, L, F)
{
    __shared__ __align__(16) float Psh[FG][NPP];  // Psh[w][j] = excl prefix before sample j
    __shared__ __align__(16) float xsh[B_N][XW];

    const int tid  = threadIdx.x;
    const int lane = tid & 31;
    const int warp = tid >> 5;
    const int s0   = blockIdx.x * TILE_L;
    const int fg0  = blockIdx.y * FG;

    // ---- stage x: exactly 128 floats per batch (max index read = 127).
    // tid<128: one LDG.128 + one STS.128. Always in-bounds (s0+127 <= 16383).
    if (tid < 128) {
        int b = tid >> 5;
        int j = tid & 31;
        float4 v = ((const float4*)(x + b * S_TOTAL + s0))[j];
        *((float4*)&xsh[b][4 * j]) = v;
    }

    // ---- sine window + fp32 prefix scan; warp w owns feature row fg0+w ----
    {
        const int f = fg0 + warp;
        // lane's 4 consecutive samples via one LDG.128 (s0+127 <= 16383 always)
        float4 v = ((const float4*)(g_sine + f * S_TOTAL + s0))[lane];
        float loc0 = v.x;
        float loc1 = loc0 + v.y;
        float loc2 = loc1 + v.z;
        float run  = loc2 + v.w;
        // exclusive scan of lane totals across the warp
        float t = run;
#pragma unroll
        for (int off = 1; off < 32; off <<= 1) {
            float n = __shfl_up_sync(0xFFFFFFFFu, t, off);
            if (lane >= off) t += n;
        }
        float excl = t - run;     // exclusive prefix before sample 4*lane
        // one aligned STS.128: exclusive prefixes at indices 4*lane .. 4*lane+3
        float4 w4;
        w4.x = excl;
        w4.y = excl + loc0;
        w4.z = excl + loc1;
        w4.w = excl + loc2;
        *((float4*)&Psh[warp][4 * lane]) = w4;
        if (lane == 31) Psh[warp][128] = excl + run;   // max index read is 128
    }
    __syncthreads();

    // ---- epilogue: thread -> (fl = tid&7, i0 = tid>>3), 2 l-passes x 4 batches ----
    const int fl = tid & 7;
    const int f  = fg0 + fl;
    const int i0 = tid >> 3;             // 0..31
    const float rk = res_kernel[f];
    const int i32 = 32 - f;
    const int i64 = 64 - f;

#pragma unroll
    for (int p = 0; p < 2; p++) {
        int i = i0 + p * 32;             // local l index, 0..63
        int l = s0 + i;
        float p0 = Psh[fl][i];
        float pa = Psh[fl][i + i32];
        float pb = Psh[fl][i + i64];
        float p3 = Psh[fl][i + 65];
        float A0 = pa - p0;              // sum sines[f, l .. l+31-f]
        float A1 = pb - pa;              // sum sines[f, l+32-f .. l+63-f]
        float A2 = p3 - pb;              // sum sines[f, l+64-f .. l+64]
        int xb = i + 2 * f;
#pragma unroll
        for (int b = 0; b < B_N; b++) {
            float r = fmaf(xsh[b][xb],     A0,
                      fmaf(xsh[b][xb + 1], A1,
                      fmaf(xsh[b][xb + 2], A2,
                           xsh[b][i + 32] * rk)));
            out[(b * L_OUT + l) * F_N + f] = r;
        }
    }
}

extern "C" void kernel_launch(void* const* d_in, const int* in_sizes, int n_in,
                              void* d_out, int out_size) {
    const float* x    = (const float*)d_in[0];
    const float* sr   = (const float*)d_in[1];
    const float* ph   = (const float*)d_in[2];
    const float* amp  = (const float*)d_in[3];
    const float* freq = (const float*)d_in[4];
    const float* rk   = (const float*)d_in[5];
    float* out = (float*)d_out;

    dim3 g1(S_TOTAL / (256 * 4), F_N);
    sine_table_kernel<<<g1, 256>>>(sr, ph, amp, freq);

    dim3 g2(L_OUT / TILE_L, F_N / FG);
    sineconv_kernel<<<g2, 256>>>(x, rk, out);
}

// round 9
// speedup vs baseline: 1.6272x; 1.2007x over previous
#include <cuda_runtime.h>

// Sineconv: out[b,l,f] = sum_{w=0}^{64} x[b, l + 2f + ((f+w)>>5)] * sines[f, l+w]
//                        + x[b, l+32] * res_kernel[f]
// sines[f,s] = amplitude[f] * sin( ((frequency[f]*19000)*2pi) * sine_range[s] + phases[f]*2pi )
//
// x factor is piecewise-constant in w over 3 ranges -> each output needs
// 3 contiguous range-sums of sines (local fp32 prefix scan) + residual.
//
// R9: single fused kernel (two kernels each paid ~3us fixed launch/ovh; in-warp
// sine chain ~300cyc is cheaper than a table LDG anyway). R8's low-MLP staging
// (1 LDG.128/thread x-stage, 1 LDG.128/lane sr window), STS.128 exclusive-
// prefix scan writes, one barrier, CF epilogue. __launch_bounds__(256,7):
// 7 CTAs/SM resident -> 1020 CTAs in a single wave (148*7=1036).

#define S_TOTAL 16384
#define L_OUT   16320
#define F_N     32
#define B_N     4
#define TILE_L  64
#define FG      8               // features per block
#define NPP     132             // Psh row stride (16B-aligned rows, CF epilogue)
#define XW      132             // xsh row stride (only 0..127 used)

// Accurate sinf via fp32 FMA Cody-Waite (exact internal products).
// |arg| <= ~1e5 here: total reduction error ~6e-8 rad.
__device__ __forceinline__ float acc_sinf(float a) {
    float kf = rintf(a * 0.63661977236758134f);          // 2/pi
    float r  = fmaf(-kf, 1.57079637050628662e+0f, a);    // c1 = float(pi/2)
    r        = fmaf(-kf, -4.37113900018624283e-8f, r);   // c2 = float(pi/2 - c1)
    int   q  = (int)kf;
    float r2 = r * r;
    float sp = fmaf(r2, fmaf(r2, fmaf(r2, -1.9841269841e-4f, 8.3333333333e-3f),
                             -1.6666666667e-1f), 1.0f);
    float s  = r * sp;
    float c  = fmaf(r2, fmaf(r2, fmaf(r2, fmaf(r2, 2.4801587302e-5f, -1.3888888889e-3f),
                             4.1666666667e-2f), -5.0e-1f), 1.0f);
    float v = (q & 1) ? c : s;
    return (q & 2) ? -v : v;
}

__global__ __launch_bounds__(256, 7) void sineconv_kernel(
    const float* __restrict__ x,          // (B, S, 1)
    const float* __restrict__ sr,         // (S,)
    const float* __restrict__ phases,     // (32,)
    const float* __restrict__ amplitude,  // (32,)
    const float* __restrict__ frequency,  // (32,)
    const float* __restrict__ res_kernel, // (32,)
    float* __restrict__ out)              // (B, L, F)
{
    __shared__ __align__(16) float Psh[FG][NPP];  // Psh[w][j] = excl prefix before sample j
    __shared__ __align__(16) float xsh[B_N][XW];

    const int tid  = threadIdx.x;
    const int lane = tid & 31;
    const int warp = tid >> 5;
    const int s0   = blockIdx.x * TILE_L;
    const int fg0  = blockIdx.y * FG;

    // ---- stage x: exactly 128 floats per batch (max index read = 127).
    // tid<128: one LDG.128 + one STS.128. Always in-bounds (s0+127 <= 16383).
    if (tid < 128) {
        int b = tid >> 5;
        int j = tid & 31;
        float4 v = ((const float4*)(x + b * S_TOTAL + s0))[j];
        *((float4*)&xsh[b][4 * j]) = v;
    }

    // ---- sines + fp32 prefix scan; warp w owns feature row fg0+w ----
    {
        const float TWO_PI = 6.28318530717958647692f;
        const int f = fg0 + warp;
        // Replicate reference fp32 rounding: ((freq*19000)*2pi)*sr + ph
        float w2  = __fmul_rn(__fmul_rn(frequency[f], 19000.0f), TWO_PI);
        float ph  = __fmul_rn(phases[f], TWO_PI);
        float amp = amplitude[f];

        // lane's 4 consecutive samples via one LDG.128 (s0+127 <= 16383 always)
        float4 sv = ((const float4*)(sr + s0))[lane];
        float v0 = __fmul_rn(amp, acc_sinf(__fadd_rn(__fmul_rn(w2, sv.x), ph)));
        float v1 = __fmul_rn(amp, acc_sinf(__fadd_rn(__fmul_rn(w2, sv.y), ph)));
        float v2 = __fmul_rn(amp, acc_sinf(__fadd_rn(__fmul_rn(w2, sv.z), ph)));
        float v3 = __fmul_rn(amp, acc_sinf(__fadd_rn(__fmul_rn(w2, sv.w), ph)));
        float loc0 = v0;
        float loc1 = loc0 + v1;
        float loc2 = loc1 + v2;
        float run  = loc2 + v3;
        // exclusive scan of lane totals across the warp
        float t = run;
#pragma unroll
        for (int off = 1; off < 32; off <<= 1) {
            float n = __shfl_up_sync(0xFFFFFFFFu, t, off);
            if (lane >= off) t += n;
        }
        float excl = t - run;     // exclusive prefix before sample 4*lane
        // one aligned STS.128: exclusive prefixes at indices 4*lane .. 4*lane+3
        float4 w4;
        w4.x = excl;
        w4.y = excl + loc0;
        w4.z = excl + loc1;
        w4.w = excl + loc2;
        *((float4*)&Psh[warp][4 * lane]) = w4;
        if (lane == 31) Psh[warp][128] = excl + run;   // max index read is 128
    }
    __syncthreads();

    // ---- epilogue: thread -> (fl = tid&7, i0 = tid>>3), 2 l-passes x 4 batches ----
    const int fl = tid & 7;
    const int f  = fg0 + fl;
    const int i0 = tid >> 3;             // 0..31
    const float rk = res_kernel[f];
    const int i32 = 32 - f;
    const int i64 = 64 - f;

#pragma unroll
    for (int p = 0; p < 2; p++) {
        int i = i0 + p * 32;             // local l index, 0..63
        int l = s0 + i;
        float p0 = Psh[fl][i];
        float pa = Psh[fl][i + i32];
        float pb = Psh[fl][i + i64];
        float p3 = Psh[fl][i + 65];
        float A0 = pa - p0;              // sum sines[f, l .. l+31-f]
        float A1 = pb - pa;              // sum sines[f, l+32-f .. l+63-f]
        float A2 = p3 - pb;              // sum sines[f, l+64-f .. l+64]
        int xb = i + 2 * f;
#pragma unroll
        for (int b = 0; b < B_N; b++) {
            float r = fmaf(xsh[b][xb],     A0,
                      fmaf(xsh[b][xb + 1], A1,
                      fmaf(xsh[b][xb + 2], A2,
                           xsh[b][i + 32] * rk)));
            out[(b * L_OUT + l) * F_N + f] = r;
        }
    }
}

extern "C" void kernel_launch(void* const* d_in, const int* in_sizes, int n_in,
                              void* d_out, int out_size) {
    const float* x    = (const float*)d_in[0];
    const float* sr   = (const float*)d_in[1];
    const float* ph   = (const float*)d_in[2];
    const float* amp  = (const float*)d_in[3];
    const float* freq = (const float*)d_in[4];
    const float* rk   = (const float*)d_in[5];
    float* out = (float*)d_out;

    dim3 grid(L_OUT / TILE_L, F_N / FG);
    sineconv_kernel<<<grid, 256>>>(x, sr, ph, amp, freq, rk, out);
}

// round 10
// speedup vs baseline: 1.6815x; 1.0333x over previous
#include <cuda_runtime.h>

// Sineconv: out[b,l,f] = sum_{w=0}^{64} x[b, l + 2f + ((f+w)>>5)] * sines[f, l+w]
//                        + x[b, l+32] * res_kernel[f]
// sines[f,s] = amplitude[f] * sin( ((frequency[f]*19000)*2pi) * sine_range[s] + phases[f]*2pi )
//
// x factor is piecewise-constant in w over 3 ranges -> each output needs
// 3 contiguous range-sums of sines (local fp32 prefix scan) + residual.
//
// R10: TILE_L 64 -> 128. Halo recompute drops 2.0x -> 1.5x (sine evals
// 1.04M -> 786K, the largest instruction block), CTAs 1020 -> 512 (single
// wave at 4 CTAs/SM). 6 samples/lane: 3x LDG.64 + 6-deep local prefix +
// warp scan + 3x STS.64 exclusive prefixes. Epilogue unchanged per output
// (4 passes). Last tile guarded (zero-fill loads, predicated stores).

#define S_TOTAL 16384
#define L_OUT   16320
#define F_N     32
#define B_N     4
#define TILE_L  128
#define FG      8               // features per block
#define NW      (TILE_L + 64)   // 192-sample window; prefix indices 0..192
#define NPP     196             // Psh row stride (784B, 16B aligned; %32==4 -> CF p0)
#define XW      196             // xsh row stride (only 0..191 used)

// Accurate sinf via fp32 FMA Cody-Waite (exact internal products).
// |arg| <= ~1e5 here: total reduction error ~6e-8 rad.
__device__ __forceinline__ float acc_sinf(float a) {
    float kf = rintf(a * 0.63661977236758134f);          // 2/pi
    float r  = fmaf(-kf, 1.57079637050628662e+0f, a);    // c1 = float(pi/2)
    r        = fmaf(-kf, -4.37113900018624283e-8f, r);   // c2 = float(pi/2 - c1)
    int   q  = (int)kf;
    float r2 = r * r;
    float sp = fmaf(r2, fmaf(r2, fmaf(r2, -1.9841269841e-4f, 8.3333333333e-3f),
                             -1.6666666667e-1f), 1.0f);
    float s  = r * sp;
    float c  = fmaf(r2, fmaf(r2, fmaf(r2, fmaf(r2, 2.4801587302e-5f, -1.3888888889e-3f),
                             4.1666666667e-2f), -5.0e-1f), 1.0f);
    float v = (q & 1) ? c : s;
    return (q & 2) ? -v : v;
}

__global__ __launch_bounds__(256, 4) void sineconv_kernel(
    const float* __restrict__ x,          // (B, S, 1)
    const float* __restrict__ sr,         // (S,)
    const float* __restrict__ phases,     // (32,)
    const float* __restrict__ amplitude,  // (32,)
    const float* __restrict__ frequency,  // (32,)
    const float* __restrict__ res_kernel, // (32,)
    float* __restrict__ out)              // (B, L, F)
{
    __shared__ __align__(16) float Psh[FG][NPP];  // Psh[w][j] = excl prefix before sample j
    __shared__ __align__(16) float xsh[B_N][XW];

    const int tid  = threadIdx.x;
    const int lane = tid & 31;
    const int warp = tid >> 5;
    const int s0   = blockIdx.x * TILE_L;
    const int fg0  = blockIdx.y * FG;

    // ---- stage x: 192 floats per batch (max index read: xb+2 = 191).
    // 192 float4 total; tid<192: one guarded LDG.128 + one STS.128.
    if (tid < 192) {
        int b = tid / 48;
        int j = tid - b * 48;             // float4 index within batch row
        float4 v = make_float4(0.f, 0.f, 0.f, 0.f);
        if (s0 + 4 * j + 3 < S_TOTAL)     // float4 is fully in or fully out
            v = ((const float4*)(x + b * S_TOTAL + s0))[j];
        *((float4*)&xsh[b][4 * j]) = v;
    }

    // ---- sines + fp32 prefix scan; warp w owns feature row fg0+w ----
    {
        const float TWO_PI = 6.28318530717958647692f;
        const int f = fg0 + warp;
        // Replicate reference fp32 rounding: ((freq*19000)*2pi)*sr + ph
        float w2  = __fmul_rn(__fmul_rn(frequency[f], 19000.0f), TWO_PI);
        float ph  = __fmul_rn(phases[f], TWO_PI);
        float amp = amplitude[f];

        // lane owns samples 6*lane .. 6*lane+5: 3 guarded LDG.64 (8B aligned;
        // each float2 starts at even s so it is fully in or fully out).
        const int j0 = 6 * lane;
        const float2* srp = (const float2*)(sr + s0 + j0);
        float2 a0 = make_float2(0.f, 0.f), a1 = a0, a2 = a0;
        if (s0 + j0 + 1 < S_TOTAL) a0 = srp[0];
        if (s0 + j0 + 3 < S_TOTAL) a1 = srp[1];
        if (s0 + j0 + 5 < S_TOTAL) a2 = srp[2];

        float v0 = __fmul_rn(amp, acc_sinf(__fadd_rn(__fmul_rn(w2, a0.x), ph)));
        float v1 = __fmul_rn(amp, acc_sinf(__fadd_rn(__fmul_rn(w2, a0.y), ph)));
        float v2 = __fmul_rn(amp, acc_sinf(__fadd_rn(__fmul_rn(w2, a1.x), ph)));
        float v3 = __fmul_rn(amp, acc_sinf(__fadd_rn(__fmul_rn(w2, a1.y), ph)));
        float v4 = __fmul_rn(amp, acc_sinf(__fadd_rn(__fmul_rn(w2, a2.x), ph)));
        float v5 = __fmul_rn(amp, acc_sinf(__fadd_rn(__fmul_rn(w2, a2.y), ph)));
        float loc0 = v0;
        float loc1 = loc0 + v1;
        float loc2 = loc1 + v2;
        float loc3 = loc2 + v3;
        float loc4 = loc3 + v4;
        float run  = loc4 + v5;
        // exclusive scan of lane totals across the warp
        float t = run;
#pragma unroll
        for (int off = 1; off < 32; off <<= 1) {
            float n = __shfl_up_sync(0xFFFFFFFFu, t, off);
            if (lane >= off) t += n;
        }
        float excl = t - run;             // exclusive prefix before sample 6*lane
        // 3x STS.64: exclusive prefixes at indices 6*lane .. 6*lane+5
        float2* pw = (float2*)&Psh[warp][j0];
        pw[0] = make_float2(excl,        excl + loc0);
        pw[1] = make_float2(excl + loc1, excl + loc2);
        pw[2] = make_float2(excl + loc3, excl + loc4);
        if (lane == 31) Psh[warp][NW] = excl + run;    // max index read is 192
    }
    __syncthreads();

    // ---- epilogue: thread -> (fl = tid&7, i0 = tid>>3), 4 l-passes x 4 batches ----
    const int fl = tid & 7;
    const int f  = fg0 + fl;
    const int i0 = tid >> 3;             // 0..31
    const float rk = res_kernel[f];
    const int i32 = 32 - f;
    const int i64 = 64 - f;

#pragma unroll
    for (int p = 0; p < 4; p++) {
        int i = i0 + p * 32;             // local l index, 0..127
        int l = s0 + i;
        float p0 = Psh[fl][i];
        float pa = Psh[fl][i + i32];
        float pb = Psh[fl][i + i64];
        float p3 = Psh[fl][i + 65];
        float A0 = pa - p0;              // sum sines[f, l .. l+31-f]
        float A1 = pb - pa;              // sum sines[f, l+32-f .. l+63-f]
        float A2 = p3 - pb;              // sum sines[f, l+64-f .. l+64]
        int xb = i + 2 * f;
        if (l < L_OUT) {
#pragma unroll
            for (int b = 0; b < B_N; b++) {
                float r = fmaf(xsh[b][xb],     A0,
                          fmaf(xsh[b][xb + 1], A1,
                          fmaf(xsh[b][xb + 2], A2,
                               xsh[b][i + 32] * rk)));
                out[(b * L_OUT + l) * F_N + f] = r;
            }
        }
    }
}

extern "C" void kernel_launch(void* const* d_in, const int* in_sizes, int n_in,
                              void* d_out, int out_size) {
    const float* x    = (const float*)d_in[0];
    const float* sr   = (const float*)d_in[1];
    const float* ph   = (const float*)d_in[2];
    const float* amp  = (const float*)d_in[3];
    const float* freq = (const float*)d_in[4];
    const float* rk   = (const float*)d_in[5];
    float* out = (float*)d_out;

    dim3 grid((L_OUT + TILE_L - 1) / TILE_L, F_N / FG);
    sineconv_kernel<<<grid, 256>>>(x, sr, ph, amp, freq, rk, out);
}